// round 5
// baseline (speedup 1.0000x reference)
#include <cuda_runtime.h>
#include <math.h>
#include <stdint.h>

#define BATCH 1024
#define FEAT  512
#define NT    64
#define CSETN 64
#define DDIM  1024

// Output layout (floats): A_real, A_imag, D_real_n, D_imag_n, CSet
#define OFF_AR 0L
#define OFF_AI 4194304L
#define OFF_DR 8388608L
#define OFF_DI 9437184L
#define OFF_CS 10485760L

#define NG_CTAS 256      // gemm CTAs: 8 m-tiles x 32 n-tiles
#define NA_CTAS 128      // A-fill CTAs (8 batches each)

__device__ __forceinline__ uint32_t f2tf32(float f) {
    uint32_t r;
    asm("cvt.rna.tf32.f32 %0, %1;" : "=r"(r) : "f"(f));
    return r;
}

__device__ __forceinline__ void mma_tf32(float* d, const uint32_t* a, const uint32_t* b) {
    asm volatile(
        "mma.sync.aligned.m16n8k8.row.col.f32.tf32.tf32.f32 "
        "{%0,%1,%2,%3}, {%4,%5,%6,%7}, {%8,%9}, {%0,%1,%2,%3};"
        : "+f"(d[0]), "+f"(d[1]), "+f"(d[2]), "+f"(d[3])
        : "r"(a[0]), "r"(a[1]), "r"(a[2]), "r"(a[3]), "r"(b[0]), "r"(b[1]));
}

// Shared memory union: gemm path vs afill path
struct SmemG {
    uint32_t As[2][128 * 20];   // [buf][row*20 + k]
    uint32_t Bs[2][64 * 20];
};
struct SmemA {
    float xs[8 * 512];          // x rows for 8 batches
    float cs[8 * 64];           // cos(theta)
    float sn[8 * 64];           // sin(theta)
};
union Smem {
    SmemG g;
    SmemA a;
};

// ---------------------------------------------------------------------------
// One launch does everything.
//  bx <  NG_CTAS : fused tf32 GEMM + normalization for Dr/Di
//  bx >= NG_CTAS : A_real/A_imag fill (incl. computing theta) + CSet copy
// ---------------------------------------------------------------------------
__global__ __launch_bounds__(128, 3)
void uber_kernel(const float* __restrict__ x,
                 const float* __restrict__ W_A, const float* __restrict__ b_A,
                 const float* __restrict__ Wr,  const float* __restrict__ br,
                 const float* __restrict__ Wi,  const float* __restrict__ bi,
                 const float* __restrict__ CSet,
                 float* __restrict__ out)
{
    __shared__ Smem smem;
    const int tid = threadIdx.x;
    const int bx  = blockIdx.x;

    if (bx < NG_CTAS) {
        // ================= GEMM path =================
        // CTA: 128 batch rows x (32 Dr cols + 32 Di cols). 4 warps,
        // warp tile: 32 rows x all 64 B-rows. smem [m][k], LDK=20.
        constexpr int LDK = 20;
        constexpr int BK  = 16;
        constexpr int NKT = FEAT / BK;   // 32

        const int lane  = tid & 31;
        const int warp  = tid >> 5;      // warpM = warp, rows warp*32..+31
        const int g     = lane >> 2;
        const int t4    = lane & 3;

        const int mBase = (bx >> 5) * 128;
        const int n0    = (bx & 31) * 32;

        float* Cr = out + OFF_DR;
        float* Ci = out + OFF_DI;

        float d[2][8][4];
#pragma unroll
        for (int i = 0; i < 2; i++)
#pragma unroll
            for (int j = 0; j < 8; j++)
#pragma unroll
                for (int v = 0; v < 4; v++) d[i][j][v] = 0.0f;

        // loader tasks: A 512 float4 (4/thread), B 256 float4 (2/thread)
        float4 pa[4], pb[2];
        int arow[4], akq[4], brow[2], bkq[2];
#pragma unroll
        for (int t = 0; t < 4; t++) {
            int ti = tid + 128 * t;
            arow[t] = ti >> 2; akq[t] = ti & 3;
        }
#pragma unroll
        for (int t = 0; t < 2; t++) {
            int ti = tid + 128 * t;
            brow[t] = ti >> 2; bkq[t] = ti & 3;
        }

#define LOADG(kt)                                                              \
        do {                                                                   \
            _Pragma("unroll")                                                  \
            for (int t = 0; t < 4; t++)                                        \
                pa[t] = *reinterpret_cast<const float4*>(                      \
                    &x[(size_t)(mBase + arow[t]) * FEAT + (kt) * BK + akq[t] * 4]); \
            _Pragma("unroll")                                                  \
            for (int t = 0; t < 2; t++) {                                      \
                const float* src = (brow[t] < 32)                              \
                    ? &Wr[(size_t)(n0 + brow[t]) * FEAT]                       \
                    : &Wi[(size_t)(n0 + brow[t] - 32) * FEAT];                 \
                pb[t] = *reinterpret_cast<const float4*>(                      \
                    &src[(kt) * BK + bkq[t] * 4]);                             \
            }                                                                  \
        } while (0)

#define STS(bf)                                                                \
        do {                                                                   \
            _Pragma("unroll")                                                  \
            for (int t = 0; t < 4; t++)                                        \
                *reinterpret_cast<uint4*>(                                     \
                    &smem.g.As[bf][arow[t] * LDK + akq[t] * 4]) =              \
                    make_uint4(f2tf32(pa[t].x), f2tf32(pa[t].y),               \
                               f2tf32(pa[t].z), f2tf32(pa[t].w));              \
            _Pragma("unroll")                                                  \
            for (int t = 0; t < 2; t++)                                        \
                *reinterpret_cast<uint4*>(                                     \
                    &smem.g.Bs[bf][brow[t] * LDK + bkq[t] * 4]) =              \
                    make_uint4(f2tf32(pb[t].x), f2tf32(pb[t].y),               \
                               f2tf32(pb[t].z), f2tf32(pb[t].w));              \
        } while (0)

        LOADG(0);
        STS(0);
        __syncthreads();

        int buf = 0;
        for (int kt = 0; kt < NKT; kt++) {
            if (kt < NKT - 1) LOADG(kt + 1);

            const uint32_t* as = smem.g.As[buf];
            const uint32_t* bs = smem.g.Bs[buf];
#pragma unroll
            for (int ks = 0; ks < 2; ks++) {
                const int kb = ks * 8 + t4;
                uint32_t af[2][4];
#pragma unroll
                for (int mi = 0; mi < 2; mi++) {
                    const int r0 = (warp * 32 + mi * 16 + g) * LDK;
                    af[mi][0] = as[r0 + kb];
                    af[mi][1] = as[r0 + 8 * LDK + kb];
                    af[mi][2] = as[r0 + kb + 4];
                    af[mi][3] = as[r0 + 8 * LDK + kb + 4];
                }
                uint32_t bq[8][2];
#pragma unroll
                for (int nj = 0; nj < 8; nj++) {
                    const int rb = (nj * 8 + g) * LDK;
                    bq[nj][0] = bs[rb + kb];
                    bq[nj][1] = bs[rb + kb + 4];
                }
#pragma unroll
                for (int mi = 0; mi < 2; mi++)
#pragma unroll
                    for (int nj = 0; nj < 8; nj++)
                        mma_tf32(d[mi][nj], af[mi], bq[nj]);
            }

            if (kt < NKT - 1) {
                STS(buf ^ 1);
                __syncthreads();
                buf ^= 1;
            }
        }
#undef LOADG
#undef STS

        // ---------- Epilogue: bias + warp-local normalization ----------
#pragma unroll
        for (int nj = 0; nj < 8; nj++) {
            const int col = n0 + (nj & 3) * 8 + 2 * t4;
            const float* bsrc = (nj < 4) ? br : bi;
            float bxv = bsrc[col];
            float byv = bsrc[col + 1];
#pragma unroll
            for (int mi = 0; mi < 2; mi++) {
                d[mi][nj][0] += bxv; d[mi][nj][1] += byv;
                d[mi][nj][2] += bxv; d[mi][nj][3] += byv;
            }
        }

        // squared sums per (mi, row-half rv, cset p)
#pragma unroll
        for (int mi = 0; mi < 2; mi++) {
            float s[2][2];
#pragma unroll
            for (int rv = 0; rv < 2; rv++)
#pragma unroll
                for (int p = 0; p < 2; p++) s[rv][p] = 0.0f;

#pragma unroll
            for (int nj = 0; nj < 8; nj++) {
                int p = (nj & 3) >> 1;
                s[0][p] += d[mi][nj][0] * d[mi][nj][0] + d[mi][nj][1] * d[mi][nj][1];
                s[1][p] += d[mi][nj][2] * d[mi][nj][2] + d[mi][nj][3] * d[mi][nj][3];
            }
#pragma unroll
            for (int rv = 0; rv < 2; rv++)
#pragma unroll
                for (int p = 0; p < 2; p++) {
                    float v = s[rv][p];
                    v += __shfl_xor_sync(0xffffffffu, v, 1);
                    v += __shfl_xor_sync(0xffffffffu, v, 2);
                    s[rv][p] = 2.0f * rsqrtf(8.0f * v);   // scale
                }

#pragma unroll
            for (int rv = 0; rv < 2; rv++) {
                const int grow = mBase + warp * 32 + mi * 16 + g + 8 * rv;
#pragma unroll
                for (int nj = 0; nj < 8; nj++) {
                    const int p   = (nj & 3) >> 1;
                    const int col = n0 + (nj & 3) * 8 + 2 * t4;
                    float sc = s[rv][p];
                    float v0 = d[mi][nj][rv * 2 + 0] * sc;
                    float v1 = d[mi][nj][rv * 2 + 1] * sc;
                    float* C = (nj < 4) ? Cr : Ci;
                    *reinterpret_cast<float2*>(&C[(size_t)grow * DDIM + col]) =
                        make_float2(v0, v1);
                }
            }
        }
    } else {
        // ================= A-fill path =================
        const int ab = bx - NG_CTAS;       // 0..127
        const int b0 = ab * 8;
        const int lane = tid & 31;
        const int warp = tid >> 5;

        // Phase 1: stage x[b0:b0+8][:] into smem (1024 float4)
        {
            const float4* xsrc = reinterpret_cast<const float4*>(x + (size_t)b0 * FEAT);
            float4* xdst = reinterpret_cast<float4*>(smem.a.xs);
#pragma unroll
            for (int t = 0; t < 8; t++)
                xdst[tid + 128 * t] = xsrc[tid + 128 * t];
        }
        __syncthreads();

        // Phase 2: theta = x @ W_A^T + b_A for 8x64 entries, warp-per-dot
        {
            const float4* xs4 = reinterpret_cast<const float4*>(smem.a.xs);
            const float4* wa4 = reinterpret_cast<const float4*>(W_A);
            for (int i = 0; i < 128; i++) {
                int pid = warp * 128 + i;        // 0..511
                int b = pid >> 6;
                int t = pid & 63;
                float sum = 0.0f;
#pragma unroll
                for (int j = 0; j < 4; j++) {
                    float4 w = wa4[t * 128 + j * 32 + lane];
                    float4 v = xs4[b * 128 + j * 32 + lane];
                    sum += w.x * v.x + w.y * v.y + w.z * v.z + w.w * v.w;
                }
                sum += __shfl_xor_sync(0xffffffffu, sum, 16);
                sum += __shfl_xor_sync(0xffffffffu, sum, 8);
                sum += __shfl_xor_sync(0xffffffffu, sum, 4);
                sum += __shfl_xor_sync(0xffffffffu, sum, 2);
                sum += __shfl_xor_sync(0xffffffffu, sum, 1);
                if (lane == 0) {
                    float th = sum + b_A[t];
                    float s, c;
                    sincosf(th, &s, &c);
                    smem.a.cs[pid] = c;
                    smem.a.sn[pid] = s;
                }
            }
        }
        __syncthreads();

        // Phase 3: write A_real / A_imag (zeros + diag), 8 batches x 2 planes
        {
            float4* Ar4 = reinterpret_cast<float4*>(out + OFF_AR) + (size_t)b0 * 1024;
            float4* Ai4 = reinterpret_cast<float4*>(out + OFF_AI) + (size_t)b0 * 1024;
            for (int i = tid; i < 8 * 64 * 16; i += 128) {
                int q = i & 15;
                int t = (i >> 4) & 63;
                int b = i >> 10;
                float4 zr = make_float4(0.f, 0.f, 0.f, 0.f);
                float4 zi = make_float4(0.f, 0.f, 0.f, 0.f);
                if (q == (t >> 2)) {
                    reinterpret_cast<float*>(&zr)[t & 3] = smem.a.cs[b * 64 + t];
                    reinterpret_cast<float*>(&zi)[t & 3] = smem.a.sn[b * 64 + t];
                }
                Ar4[i] = zr;
                Ai4[i] = zi;
            }
        }

        // Phase 4: CSet passthrough (first afill CTA only)
        if (ab == 0) {
            const float4* csrc = reinterpret_cast<const float4*>(CSet);
            float4* cdst = reinterpret_cast<float4*>(out + OFF_CS);
#pragma unroll
            for (int t = 0; t < 32; t++)
                cdst[tid + 128 * t] = csrc[tid + 128 * t];
        }
    }
}

extern "C" void kernel_launch(void* const* d_in, const int* in_sizes, int n_in,
                              void* d_out, int out_size)
{
    const float* x    = (const float*)d_in[0];
    const float* W_A  = (const float*)d_in[1];
    const float* b_A  = (const float*)d_in[2];
    const float* W_Dr = (const float*)d_in[3];
    const float* b_Dr = (const float*)d_in[4];
    const float* W_Di = (const float*)d_in[5];
    const float* b_Di = (const float*)d_in[6];
    const float* CSet = (const float*)d_in[7];
    float* out = (float*)d_out;

    uber_kernel<<<NG_CTAS + NA_CTAS, 128>>>(
        x, W_A, b_A, W_Dr, b_Dr, W_Di, b_Di, CSet, out);
}

// round 6
// speedup vs baseline: 1.2687x; 1.2687x over previous
#include <cuda_runtime.h>
#include <math.h>
#include <stdint.h>

#define BATCH 1024
#define FEAT  512
#define NT    64
#define CSETN 64
#define DDIM  1024

// Output layout (floats): A_real, A_imag, D_real_n, D_imag_n, CSet
#define OFF_AR 0L
#define OFF_AI 4194304L
#define OFF_DR 8388608L
#define OFF_DI 9437184L
#define OFF_CS 10485760L

__device__ __forceinline__ uint32_t f2tf32(float f) {
    uint32_t r;
    asm("cvt.rna.tf32.f32 %0, %1;" : "=r"(r) : "f"(f));
    return r;
}

__device__ __forceinline__ void mma_tf32(float* d, const uint32_t* a, const uint32_t* b) {
    asm volatile(
        "mma.sync.aligned.m16n8k8.row.col.f32.tf32.tf32.f32 "
        "{%0,%1,%2,%3}, {%4,%5,%6,%7}, {%8,%9}, {%0,%1,%2,%3};"
        : "+f"(d[0]), "+f"(d[1]), "+f"(d[2]), "+f"(d[3])
        : "r"(a[0]), "r"(a[1]), "r"(a[2]), "r"(a[3]), "r"(b[0]), "r"(b[1]));
}

// ---------------------------------------------------------------------------
// Fused tf32 GEMM + normalization. 256 CTAs x 128 threads.
// CTA: 128 batch rows x (32 Dr cols + 32 Di cols). 4 warps, warp tile
// 32 rows x all 64 B-rows. smem [m][k], LDK=20 (conflict-free LDS).
// ---------------------------------------------------------------------------
__global__ __launch_bounds__(128, 3)
void dgemm_kernel(const float* __restrict__ x,
                  const float* __restrict__ Wr, const float* __restrict__ br,
                  const float* __restrict__ Wi, const float* __restrict__ bi,
                  float* __restrict__ out)
{
    constexpr int LDK = 20;
    constexpr int BK  = 16;
    constexpr int NKT = FEAT / BK;   // 32

    __shared__ uint32_t As[2][128 * LDK];
    __shared__ uint32_t Bs[2][64 * LDK];

    const int tid   = threadIdx.x;
    const int lane  = tid & 31;
    const int warp  = tid >> 5;
    const int g     = lane >> 2;
    const int t4    = lane & 3;
    const int bx    = blockIdx.x;

    const int mBase = (bx >> 5) * 128;
    const int n0    = (bx & 31) * 32;

    float* Cr = out + OFF_DR;
    float* Ci = out + OFF_DI;

    float d[2][8][4];
#pragma unroll
    for (int i = 0; i < 2; i++)
#pragma unroll
        for (int j = 0; j < 8; j++)
#pragma unroll
            for (int v = 0; v < 4; v++) d[i][j][v] = 0.0f;

    float4 pa[4], pb[2];
    int arow[4], akq[4], brow[2], bkq[2];
#pragma unroll
    for (int t = 0; t < 4; t++) {
        int ti = tid + 128 * t;
        arow[t] = ti >> 2; akq[t] = ti & 3;
    }
#pragma unroll
    for (int t = 0; t < 2; t++) {
        int ti = tid + 128 * t;
        brow[t] = ti >> 2; bkq[t] = ti & 3;
    }

#define LOADG(kt)                                                              \
    do {                                                                       \
        _Pragma("unroll")                                                      \
        for (int t = 0; t < 4; t++)                                            \
            pa[t] = *reinterpret_cast<const float4*>(                          \
                &x[(size_t)(mBase + arow[t]) * FEAT + (kt) * BK + akq[t] * 4]); \
        _Pragma("unroll")                                                      \
        for (int t = 0; t < 2; t++) {                                          \
            const float* src = (brow[t] < 32)                                  \
                ? &Wr[(size_t)(n0 + brow[t]) * FEAT]                           \
                : &Wi[(size_t)(n0 + brow[t] - 32) * FEAT];                     \
            pb[t] = *reinterpret_cast<const float4*>(                          \
                &src[(kt) * BK + bkq[t] * 4]);                                 \
        }                                                                      \
    } while (0)

#define STS(bf)                                                                \
    do {                                                                       \
        _Pragma("unroll")                                                      \
        for (int t = 0; t < 4; t++)                                            \
            *reinterpret_cast<uint4*>(&As[bf][arow[t] * LDK + akq[t] * 4]) =   \
                make_uint4(f2tf32(pa[t].x), f2tf32(pa[t].y),                   \
                           f2tf32(pa[t].z), f2tf32(pa[t].w));                  \
        _Pragma("unroll")                                                      \
        for (int t = 0; t < 2; t++)                                            \
            *reinterpret_cast<uint4*>(&Bs[bf][brow[t] * LDK + bkq[t] * 4]) =   \
                make_uint4(f2tf32(pb[t].x), f2tf32(pb[t].y),                   \
                           f2tf32(pb[t].z), f2tf32(pb[t].w));                  \
    } while (0)

    LOADG(0);
    STS(0);
    __syncthreads();

    int buf = 0;
    for (int kt = 0; kt < NKT; kt++) {
        if (kt < NKT - 1) LOADG(kt + 1);

        const uint32_t* as = As[buf];
        const uint32_t* bs = Bs[buf];
#pragma unroll
        for (int ks = 0; ks < 2; ks++) {
            const int kb = ks * 8 + t4;
            uint32_t af[2][4];
#pragma unroll
            for (int mi = 0; mi < 2; mi++) {
                const int r0 = (warp * 32 + mi * 16 + g) * LDK;
                af[mi][0] = as[r0 + kb];
                af[mi][1] = as[r0 + 8 * LDK + kb];
                af[mi][2] = as[r0 + kb + 4];
                af[mi][3] = as[r0 + 8 * LDK + kb + 4];
            }
            uint32_t bq[8][2];
#pragma unroll
            for (int nj = 0; nj < 8; nj++) {
                const int rb = (nj * 8 + g) * LDK;
                bq[nj][0] = bs[rb + kb];
                bq[nj][1] = bs[rb + kb + 4];
            }
#pragma unroll
            for (int mi = 0; mi < 2; mi++)
#pragma unroll
                for (int nj = 0; nj < 8; nj++)
                    mma_tf32(d[mi][nj], af[mi], bq[nj]);
        }

        if (kt < NKT - 1) {
            STS(buf ^ 1);
            __syncthreads();
            buf ^= 1;
        }
    }
#undef LOADG
#undef STS

    // ---------- Epilogue: bias + warp-local normalization ----------
#pragma unroll
    for (int nj = 0; nj < 8; nj++) {
        const int col = n0 + (nj & 3) * 8 + 2 * t4;
        const float* bsrc = (nj < 4) ? br : bi;
        float bxv = bsrc[col];
        float byv = bsrc[col + 1];
#pragma unroll
        for (int mi = 0; mi < 2; mi++) {
            d[mi][nj][0] += bxv; d[mi][nj][1] += byv;
            d[mi][nj][2] += bxv; d[mi][nj][3] += byv;
        }
    }

#pragma unroll
    for (int mi = 0; mi < 2; mi++) {
        float s[2][2];
#pragma unroll
        for (int rv = 0; rv < 2; rv++)
#pragma unroll
            for (int p = 0; p < 2; p++) s[rv][p] = 0.0f;

#pragma unroll
        for (int nj = 0; nj < 8; nj++) {
            int p = (nj & 3) >> 1;
            s[0][p] += d[mi][nj][0] * d[mi][nj][0] + d[mi][nj][1] * d[mi][nj][1];
            s[1][p] += d[mi][nj][2] * d[mi][nj][2] + d[mi][nj][3] * d[mi][nj][3];
        }
#pragma unroll
        for (int rv = 0; rv < 2; rv++)
#pragma unroll
            for (int p = 0; p < 2; p++) {
                float v = s[rv][p];
                v += __shfl_xor_sync(0xffffffffu, v, 1);
                v += __shfl_xor_sync(0xffffffffu, v, 2);
                s[rv][p] = 2.0f * rsqrtf(8.0f * v);
            }

#pragma unroll
        for (int rv = 0; rv < 2; rv++) {
            const int grow = mBase + warp * 32 + mi * 16 + g + 8 * rv;
#pragma unroll
            for (int nj = 0; nj < 8; nj++) {
                const int p   = (nj & 3) >> 1;
                const int col = n0 + (nj & 3) * 8 + 2 * t4;
                float sc = s[rv][p];
                float v0 = d[mi][nj][rv * 2 + 0] * sc;
                float v1 = d[mi][nj][rv * 2 + 1] * sc;
                float* C = (nj < 4) ? Cr : Ci;
                *reinterpret_cast<float2*>(&C[(size_t)grow * DDIM + col]) =
                    make_float2(v0, v1);
            }
        }
    }
}

// ---------------------------------------------------------------------------
// A-fill: compute theta for 8 batches, write A_real/A_imag; CTA 0 copies CSet.
// 128 CTAs x 256 threads.
// ---------------------------------------------------------------------------
__global__ __launch_bounds__(256, 2)
void afill_kernel(const float* __restrict__ x,
                  const float* __restrict__ W_A, const float* __restrict__ b_A,
                  const float* __restrict__ CSet,
                  float* __restrict__ out)
{
    __shared__ float xs[8 * 512];
    __shared__ float cs[8 * 64];
    __shared__ float sn[8 * 64];

    const int tid  = threadIdx.x;
    const int lane = tid & 31;
    const int warp = tid >> 5;        // 0..7
    const int b0   = blockIdx.x * 8;

    // Phase 1: stage x rows
    {
        const float4* xsrc = reinterpret_cast<const float4*>(x + (size_t)b0 * FEAT);
        float4* xdst = reinterpret_cast<float4*>(xs);
#pragma unroll
        for (int t = 0; t < 4; t++)
            xdst[tid + 256 * t] = xsrc[tid + 256 * t];
    }
    __syncthreads();

    // Phase 2: theta = x @ W_A^T + b_A  (512 dots, 8 warps -> 64 each)
    {
        const float4* xs4 = reinterpret_cast<const float4*>(xs);
        const float4* wa4 = reinterpret_cast<const float4*>(W_A);
#pragma unroll 4
        for (int i = 0; i < 64; i++) {
            int pid = warp * 64 + i;        // 0..511
            int b = pid >> 6;
            int t = pid & 63;
            float sum = 0.0f;
#pragma unroll
            for (int j = 0; j < 4; j++) {
                float4 w = wa4[t * 128 + j * 32 + lane];
                float4 v = xs4[b * 128 + j * 32 + lane];
                sum += w.x * v.x + w.y * v.y + w.z * v.z + w.w * v.w;
            }
            sum += __shfl_xor_sync(0xffffffffu, sum, 16);
            sum += __shfl_xor_sync(0xffffffffu, sum, 8);
            sum += __shfl_xor_sync(0xffffffffu, sum, 4);
            sum += __shfl_xor_sync(0xffffffffu, sum, 2);
            sum += __shfl_xor_sync(0xffffffffu, sum, 1);
            if (lane == 0) {
                float th = sum + b_A[t];
                float s, c;
                sincosf(th, &s, &c);
                cs[pid] = c;
                sn[pid] = s;
            }
        }
    }
    __syncthreads();

    // Phase 3: A_real / A_imag zeros + diagonal
    {
        float4* Ar4 = reinterpret_cast<float4*>(out + OFF_AR) + (size_t)b0 * 1024;
        float4* Ai4 = reinterpret_cast<float4*>(out + OFF_AI) + (size_t)b0 * 1024;
#pragma unroll 4
        for (int i = tid; i < 8 * 64 * 16; i += 256) {
            int q = i & 15;
            int t = (i >> 4) & 63;
            int b = i >> 10;
            float4 zr = make_float4(0.f, 0.f, 0.f, 0.f);
            float4 zi = make_float4(0.f, 0.f, 0.f, 0.f);
            if (q == (t >> 2)) {
                reinterpret_cast<float*>(&zr)[t & 3] = cs[b * 64 + t];
                reinterpret_cast<float*>(&zi)[t & 3] = sn[b * 64 + t];
            }
            Ar4[i] = zr;
            Ai4[i] = zi;
        }
    }

    // Phase 4: CSet passthrough (CTA 0)
    if (blockIdx.x == 0) {
        const float4* csrc = reinterpret_cast<const float4*>(CSet);
        float4* cdst = reinterpret_cast<float4*>(out + OFF_CS);
#pragma unroll
        for (int t = 0; t < 16; t++)
            cdst[tid + 256 * t] = csrc[tid + 256 * t];
    }
}

extern "C" void kernel_launch(void* const* d_in, const int* in_sizes, int n_in,
                              void* d_out, int out_size)
{
    const float* x    = (const float*)d_in[0];
    const float* W_A  = (const float*)d_in[1];
    const float* b_A  = (const float*)d_in[2];
    const float* W_Dr = (const float*)d_in[3];
    const float* b_Dr = (const float*)d_in[4];
    const float* W_Di = (const float*)d_in[5];
    const float* b_Di = (const float*)d_in[6];
    const float* CSet = (const float*)d_in[7];
    float* out = (float*)d_out;

    // Lazily create a secondary stream + fork/join events on the first
    // (uncaptured correctness) call; reused as graph parallel branches
    // during capture.
    static cudaStream_t s2 = nullptr;
    static cudaEvent_t evFork = nullptr, evJoin = nullptr;
    static bool init_tried = false;
    if (!init_tried) {
        init_tried = true;
        if (cudaStreamCreateWithFlags(&s2, cudaStreamNonBlocking) != cudaSuccess)
            s2 = nullptr;
        if (s2) {
            if (cudaEventCreateWithFlags(&evFork, cudaEventDisableTiming) != cudaSuccess ||
                cudaEventCreateWithFlags(&evJoin, cudaEventDisableTiming) != cudaSuccess) {
                evFork = evJoin = nullptr;
            }
        }
    }

    const bool forked = (s2 && evFork && evJoin);

    if (forked) {
        cudaEventRecord(evFork, 0);
        cudaStreamWaitEvent(s2, evFork, 0);
    }

    // Branch A (default stream): D GEMM + fused normalization
    dgemm_kernel<<<256, 128>>>(x, W_Dr, b_Dr, W_Di, b_Di, out);

    // Branch B: theta + A planes + CSet
    if (forked) {
        afill_kernel<<<128, 256, 0, s2>>>(x, W_A, b_A, CSet, out);
        cudaEventRecord(evJoin, s2);
        cudaStreamWaitEvent(0, evJoin, 0);
    } else {
        afill_kernel<<<128, 256>>>(x, W_A, b_A, CSet, out);
    }
}

// round 10
// speedup vs baseline: 1.5794x; 1.2449x over previous
#include <cuda_runtime.h>
#include <math.h>
#include <stdint.h>

#define BATCH 1024
#define FEAT  512
#define NT    64
#define CSETN 64
#define DDIM  1024

// Output layout (floats): A_real, A_imag, D_real_n, D_imag_n, CSet
#define OFF_AR 0L
#define OFF_AI 4194304L
#define OFF_DR 8388608L
#define OFF_DI 9437184L
#define OFF_CS 10485760L

__device__ float g_cs[BATCH * NT];
__device__ float g_sn[BATCH * NT];

__device__ __forceinline__ uint32_t f2tf32(float f) {
    uint32_t r;
    asm("cvt.rna.tf32.f32 %0, %1;" : "=r"(r) : "f"(f));
    return r;
}

__device__ __forceinline__ void mma_tf32(float* d, const uint32_t* a, const uint32_t* b) {
    asm volatile(
        "mma.sync.aligned.m16n8k8.row.col.f32.tf32.tf32.f32 "
        "{%0,%1,%2,%3}, {%4,%5,%6,%7}, {%8,%9}, {%0,%1,%2,%3};"
        : "+f"(d[0]), "+f"(d[1]), "+f"(d[2]), "+f"(d[3])
        : "r"(a[0]), "r"(a[1]), "r"(a[2]), "r"(a[3]), "r"(b[0]), "r"(b[1]));
}

// ---------------------------------------------------------------------------
// Fused tf32 GEMM + normalization. 256 CTAs x 128 threads. (unchanged, R5)
// ---------------------------------------------------------------------------
__global__ __launch_bounds__(128, 3)
void dgemm_kernel(const float* __restrict__ x,
                  const float* __restrict__ Wr, const float* __restrict__ br,
                  const float* __restrict__ Wi, const float* __restrict__ bi,
                  float* __restrict__ out)
{
    constexpr int LDK = 20;
    constexpr int BK  = 16;
    constexpr int NKT = FEAT / BK;   // 32

    __shared__ uint32_t As[2][128 * LDK];
    __shared__ uint32_t Bs[2][64 * LDK];

    const int tid   = threadIdx.x;
    const int lane  = tid & 31;
    const int warp  = tid >> 5;
    const int g     = lane >> 2;
    const int t4    = lane & 3;
    const int bx    = blockIdx.x;

    const int mBase = (bx >> 5) * 128;
    const int n0    = (bx & 31) * 32;

    float* Cr = out + OFF_DR;
    float* Ci = out + OFF_DI;

    float d[2][8][4];
#pragma unroll
    for (int i = 0; i < 2; i++)
#pragma unroll
        for (int j = 0; j < 8; j++)
#pragma unroll
            for (int v = 0; v < 4; v++) d[i][j][v] = 0.0f;

    float4 pa[4], pb[2];
    int arow[4], akq[4], brow[2], bkq[2];
#pragma unroll
    for (int t = 0; t < 4; t++) {
        int ti = tid + 128 * t;
        arow[t] = ti >> 2; akq[t] = ti & 3;
    }
#pragma unroll
    for (int t = 0; t < 2; t++) {
        int ti = tid + 128 * t;
        brow[t] = ti >> 2; bkq[t] = ti & 3;
    }

#define LOADG(kt)                                                              \
    do {                                                                       \
        _Pragma("unroll")                                                      \
        for (int t = 0; t < 4; t++)                                            \
            pa[t] = *reinterpret_cast<const float4*>(                          \
                &x[(size_t)(mBase + arow[t]) * FEAT + (kt) * BK + akq[t] * 4]); \
        _Pragma("unroll")                                                      \
        for (int t = 0; t < 2; t++) {                                          \
            const float* src = (brow[t] < 32)                                  \
                ? &Wr[(size_t)(n0 + brow[t]) * FEAT]                           \
                : &Wi[(size_t)(n0 + brow[t] - 32) * FEAT];                     \
            pb[t] = *reinterpret_cast<const float4*>(                          \
                &src[(kt) * BK + bkq[t] * 4]);                                 \
        }                                                                      \
    } while (0)

#define STS(bf)                                                                \
    do {                                                                       \
        _Pragma("unroll")                                                      \
        for (int t = 0; t < 4; t++)                                            \
            *reinterpret_cast<uint4*>(&As[bf][arow[t] * LDK + akq[t] * 4]) =   \
                make_uint4(f2tf32(pa[t].x), f2tf32(pa[t].y),                   \
                           f2tf32(pa[t].z), f2tf32(pa[t].w));                  \
        _Pragma("unroll")                                                      \
        for (int t = 0; t < 2; t++)                                            \
            *reinterpret_cast<uint4*>(&Bs[bf][brow[t] * LDK + bkq[t] * 4]) =   \
                make_uint4(f2tf32(pb[t].x), f2tf32(pb[t].y),                   \
                           f2tf32(pb[t].z), f2tf32(pb[t].w));                  \
    } while (0)

    LOADG(0);
    STS(0);
    __syncthreads();

    int buf = 0;
    for (int kt = 0; kt < NKT; kt++) {
        if (kt < NKT - 1) LOADG(kt + 1);

        const uint32_t* as = As[buf];
        const uint32_t* bs = Bs[buf];
#pragma unroll
        for (int ks = 0; ks < 2; ks++) {
            const int kb = ks * 8 + t4;
            uint32_t af[2][4];
#pragma unroll
            for (int mi = 0; mi < 2; mi++) {
                const int r0 = (warp * 32 + mi * 16 + g) * LDK;
                af[mi][0] = as[r0 + kb];
                af[mi][1] = as[r0 + 8 * LDK + kb];
                af[mi][2] = as[r0 + kb + 4];
                af[mi][3] = as[r0 + 8 * LDK + kb + 4];
            }
            uint32_t bq[8][2];
#pragma unroll
            for (int nj = 0; nj < 8; nj++) {
                const int rb = (nj * 8 + g) * LDK;
                bq[nj][0] = bs[rb + kb];
                bq[nj][1] = bs[rb + kb + 4];
            }
#pragma unroll
            for (int mi = 0; mi < 2; mi++)
#pragma unroll
                for (int nj = 0; nj < 8; nj++)
                    mma_tf32(d[mi][nj], af[mi], bq[nj]);
        }

        if (kt < NKT - 1) {
            STS(buf ^ 1);
            __syncthreads();
            buf ^= 1;
        }
    }
#undef LOADG
#undef STS

    // ---------- Epilogue: bias + warp-local normalization ----------
#pragma unroll
    for (int nj = 0; nj < 8; nj++) {
        const int col = n0 + (nj & 3) * 8 + 2 * t4;
        const float* bsrc = (nj < 4) ? br : bi;
        float bxv = bsrc[col];
        float byv = bsrc[col + 1];
#pragma unroll
        for (int mi = 0; mi < 2; mi++) {
            d[mi][nj][0] += bxv; d[mi][nj][1] += byv;
            d[mi][nj][2] += bxv; d[mi][nj][3] += byv;
        }
    }

#pragma unroll
    for (int mi = 0; mi < 2; mi++) {
        float s[2][2];
#pragma unroll
        for (int rv = 0; rv < 2; rv++)
#pragma unroll
            for (int p = 0; p < 2; p++) s[rv][p] = 0.0f;

#pragma unroll
        for (int nj = 0; nj < 8; nj++) {
            int p = (nj & 3) >> 1;
            s[0][p] += d[mi][nj][0] * d[mi][nj][0] + d[mi][nj][1] * d[mi][nj][1];
            s[1][p] += d[mi][nj][2] * d[mi][nj][2] + d[mi][nj][3] * d[mi][nj][3];
        }
#pragma unroll
        for (int rv = 0; rv < 2; rv++)
#pragma unroll
            for (int p = 0; p < 2; p++) {
                float v = s[rv][p];
                v += __shfl_xor_sync(0xffffffffu, v, 1);
                v += __shfl_xor_sync(0xffffffffu, v, 2);
                s[rv][p] = 2.0f * rsqrtf(8.0f * v);
            }

#pragma unroll
        for (int rv = 0; rv < 2; rv++) {
            const int grow = mBase + warp * 32 + mi * 16 + g + 8 * rv;
#pragma unroll
            for (int nj = 0; nj < 8; nj++) {
                const int p   = (nj & 3) >> 1;
                const int col = n0 + (nj & 3) * 8 + 2 * t4;
                float sc = s[rv][p];
                float v0 = d[mi][nj][rv * 2 + 0] * sc;
                float v1 = d[mi][nj][rv * 2 + 1] * sc;
                float* C = (nj < 4) ? Cr : Ci;
                *reinterpret_cast<float2*>(&C[(size_t)grow * DDIM + col]) =
                    make_float2(v0, v1);
            }
        }
    }
}

// ---------------------------------------------------------------------------
// theta SGEMM: cs/sn = cos/sin(x @ W_A^T + b_A). SIMT, 16 CTAs x 256 thr.
// ---------------------------------------------------------------------------
template <int BM, int BN, int BK, int TM, int TN>
__global__ __launch_bounds__((BM / TM) * (BN / TN))
void theta_kernel(const float* __restrict__ A,
                  const float* __restrict__ W, const float* __restrict__ bias,
                  float* __restrict__ Ccs, float* __restrict__ Csn)
{
    constexpr int NTH = (BM / TM) * (BN / TN);
    __shared__ float As[BK][BM + 4];
    __shared__ float Bs[BK][BN + 4];

    const int tid  = threadIdx.x;
    const int tcol = tid % (BN / TN);
    const int trow = tid / (BN / TN);
    const int mBase = blockIdx.x * BM;

    float acc[TM][TN];
#pragma unroll
    for (int i = 0; i < TM; i++)
#pragma unroll
        for (int j = 0; j < TN; j++) acc[i][j] = 0.0f;

    for (int k0 = 0; k0 < FEAT; k0 += BK) {
        for (int i = tid; i < BM * BK / 4; i += NTH) {
            int r  = i / (BK / 4);
            int kc = (i % (BK / 4)) * 4;
            float4 v = *reinterpret_cast<const float4*>(
                &A[(size_t)(mBase + r) * FEAT + k0 + kc]);
            As[kc + 0][r] = v.x; As[kc + 1][r] = v.y;
            As[kc + 2][r] = v.z; As[kc + 3][r] = v.w;
        }
        for (int i = tid; i < BN * BK / 4; i += NTH) {
            int r  = i / (BK / 4);
            int kc = (i % (BK / 4)) * 4;
            float4 v = *reinterpret_cast<const float4*>(
                &W[(size_t)r * FEAT + k0 + kc]);
            Bs[kc + 0][r] = v.x; Bs[kc + 1][r] = v.y;
            Bs[kc + 2][r] = v.z; Bs[kc + 3][r] = v.w;
        }
        __syncthreads();

#pragma unroll
        for (int k = 0; k < BK; k++) {
            float am[TM], bn[TN];
#pragma unroll
            for (int i = 0; i < TM; i++) am[i] = As[k][trow * TM + i];
#pragma unroll
            for (int j = 0; j < TN; j++) bn[j] = Bs[k][tcol * TN + j];
#pragma unroll
            for (int i = 0; i < TM; i++)
#pragma unroll
                for (int j = 0; j < TN; j++) acc[i][j] += am[i] * bn[j];
        }
        __syncthreads();
    }

    const int col = tcol * TN;
#pragma unroll
    for (int i = 0; i < TM; i++) {
        int row = mBase + trow * TM + i;
#pragma unroll
        for (int j = 0; j < TN; j++) {
            float th = acc[i][j] + bias[col + j];
            float s, c;
            sincosf(th, &s, &c);
            Ccs[(size_t)row * NT + col + j] = c;
            Csn[(size_t)row * NT + col + j] = s;
        }
    }
}

// ---------------------------------------------------------------------------
// A_real / A_imag zeros + diag fill (1 thread per float4 slot); tail = CSet.
// ---------------------------------------------------------------------------
__global__ __launch_bounds__(256)
void afill_kernel(const float* __restrict__ cs, const float* __restrict__ sn,
                  const float* __restrict__ csrc, float* __restrict__ out)
{
    int idx = blockIdx.x * blockDim.x + threadIdx.x;
    if (idx < BATCH * NT * 16) {
        int q = idx & 15;
        int t = (idx >> 4) & 63;
        int b = idx >> 10;

        float4 zr = make_float4(0.f, 0.f, 0.f, 0.f);
        float4 zi = make_float4(0.f, 0.f, 0.f, 0.f);
        if (q == (t >> 2)) {
            reinterpret_cast<float*>(&zr)[t & 3] = cs[b * NT + t];
            reinterpret_cast<float*>(&zi)[t & 3] = sn[b * NT + t];
        }
        reinterpret_cast<float4*>(out + OFF_AR)[idx] = zr;
        reinterpret_cast<float4*>(out + OFF_AI)[idx] = zi;
    } else {
        int c = idx - BATCH * NT * 16;
        if (c < CSETN * NT) {
            reinterpret_cast<float4*>(out + OFF_CS)[c] =
                reinterpret_cast<const float4*>(csrc)[c];
        }
    }
}

extern "C" void kernel_launch(void* const* d_in, const int* in_sizes, int n_in,
                              void* d_out, int out_size)
{
    const float* x    = (const float*)d_in[0];
    const float* W_A  = (const float*)d_in[1];
    const float* b_A  = (const float*)d_in[2];
    const float* W_Dr = (const float*)d_in[3];
    const float* b_Dr = (const float*)d_in[4];
    const float* W_Di = (const float*)d_in[5];
    const float* b_Di = (const float*)d_in[6];
    const float* CSet = (const float*)d_in[7];
    float* out = (float*)d_out;

    float *cs = nullptr, *sn = nullptr;
    cudaGetSymbolAddress((void**)&cs, g_cs);
    cudaGetSymbolAddress((void**)&sn, g_sn);

    static cudaStream_t s2 = nullptr;
    static cudaEvent_t evFork = nullptr, evJoin = nullptr;
    static bool init_tried = false;
    if (!init_tried) {
        init_tried = true;
        if (cudaStreamCreateWithFlags(&s2, cudaStreamNonBlocking) != cudaSuccess)
            s2 = nullptr;
        if (s2) {
            if (cudaEventCreateWithFlags(&evFork, cudaEventDisableTiming) != cudaSuccess ||
                cudaEventCreateWithFlags(&evJoin, cudaEventDisableTiming) != cudaSuccess) {
                evFork = evJoin = nullptr;
            }
        }
    }
    const bool forked = (s2 && evFork && evJoin);

    if (forked) {
        cudaEventRecord(evFork, 0);
        cudaStreamWaitEvent(s2, evFork, 0);
    }

    // Branch A (default stream): D GEMM + fused normalization
    dgemm_kernel<<<256, 128>>>(x, W_Dr, b_Dr, W_Di, b_Di, out);

    // Branch B: theta (cos/sin) -> A planes + CSet
    {
        cudaStream_t sb = forked ? s2 : (cudaStream_t)0;
        theta_kernel<64, 64, 16, 4, 4><<<BATCH / 64, 256, 0, sb>>>(
            x, W_A, b_A, cs, sn);
        int total = BATCH * NT * 16 + CSETN * NT;
        afill_kernel<<<(total + 255) / 256, 256, 0, sb>>>(cs, sn, CSet, out);
        if (forked) {
            cudaEventRecord(evJoin, s2);
            cudaStreamWaitEvent(0, evJoin, 0);
        }
    }
}